// round 16
// baseline (speedup 1.0000x reference)
#include <cuda_runtime.h>
#include <math.h>
#include <stdint.h>

#define Bb 64
#define Ss 1024
#define Ee 300
#define Hh 256
#define Gg 1024
#define DHh 512
#define DAa 64
#define Rr 16
#define MHh 512
#define RKk 8192

#define ET_OFF   0
#define PRT_OFF  3200
#define POPT_OFF 3968
#define H_OFF    4480
#define C_OFF    37248
#define PEN_OFF  70016
#define A_OFF    70017

__device__ float g_xw_f[Bb * Ss * Gg];
__device__ float g_xw_b[Bb * Ss * Gg];
__device__ float g_S1t[DHh * DAa];
__device__ float g_Hout[Bb * Ss * DHh];
__device__ float g_s2[Bb * Rr * Ss];   // [b][r][t]
__device__ float g_BM[Bb * RKk];
__device__ float g_hid[3 * Bb * MHh];
__device__ float g_pp[Bb];

__device__ __forceinline__ float fsig(float x) {
    return __fdividef(1.f, 1.f + __expf(-x));
}
__device__ __forceinline__ float ftanh(float x) {
    return 1.f - __fdividef(2.f, __expf(2.f * x) + 1.f);
}
__device__ __forceinline__ void ffma2(unsigned long long& d, unsigned long long a,
                                      unsigned long long b) {
    asm("fma.rn.f32x2 %0, %1, %2, %0;" : "+l"(d) : "l"(a), "l"(b));
}
__device__ __forceinline__ unsigned long long pack2(float x, float y) {
    unsigned long long r;
    asm("mov.b64 %0, {%1, %2};" : "=l"(r) : "r"(__float_as_uint(x)), "r"(__float_as_uint(y)));
    return r;
}
__device__ __forceinline__ float hadd2(unsigned long long v) {
    union { unsigned long long u; float2 f; } cv;
    cv.u = v;
    return cv.f.x + cv.f.y;
}
__device__ __forceinline__ uint32_t smem_u32(const void* p) {
    return (uint32_t)__cvta_generic_to_shared(p);
}
__device__ __forceinline__ void stc_f32_rank(uint32_t local_addr, uint32_t rank, float v) {
    asm volatile(
        "{\n\t.reg .b32 ra;\n\t"
        "mapa.shared::cluster.u32 ra, %0, %1;\n\t"
        "st.shared::cluster.f32 [ra], %2;\n\t}"
        :: "r"(local_addr), "r"(rank), "f"(v) : "memory");
}
__device__ __forceinline__ void mbar_init(uint32_t a, uint32_t cnt) {
    asm volatile("mbarrier.init.shared.b64 [%0], %1;" :: "r"(a), "r"(cnt) : "memory");
}
__device__ __forceinline__ void mbar_arrive_peer(uint32_t local_addr, uint32_t rank) {
    asm volatile(
        "{\n\t.reg .b32 ra;\n\t"
        "mapa.shared::cluster.u32 ra, %0, %1;\n\t"
        "mbarrier.arrive.shared::cluster.b64 _, [ra];\n\t}"
        :: "r"(local_addr), "r"(rank) : "memory");
}
__device__ __forceinline__ void mbar_waitc(uint32_t addr, uint32_t parity) {
    uint32_t done;
    do {
        asm volatile(
            "{\n\t.reg .pred p;\n\t"
            "mbarrier.try_wait.parity.acquire.cluster.shared::cta.b64 p, [%1], %2;\n\t"
            "selp.b32 %0, 1, 0, p;\n\t}"
            : "=r"(done) : "r"(addr), "r"(parity) : "memory");
    } while (!done);
}
#define FENCE_CLUSTER() asm volatile("fence.acq_rel.cluster;" ::: "memory")
#define GROUP_BAR(id) asm volatile("bar.sync %0, %1;" :: "r"(id), "r"(256) : "memory")
#define CLUSTER_SYNC() do { \
    asm volatile("barrier.cluster.arrive.aligned;" ::: "memory"); \
    asm volatile("barrier.cluster.wait.aligned;" ::: "memory"); \
} while (0)

// ---- no-op launch to align ncu's captured slot onto k_lstm
__global__ void k_noop() {
    if (threadIdx.x == 1024) g_pp[0] = 0.f;   // never true
}

// ---- S1 transpose only (64x512 -> 512x64)
__global__ void k_transpose(const float* __restrict__ S1) {
    int c0 = blockIdx.x * 32, r0 = blockIdx.y * 32;
    __shared__ float tile[32][33];
    int tx = threadIdx.x, ty = threadIdx.y;
#pragma unroll
    for (int i = 0; i < 4; i++)
        tile[ty + i * 8][tx] = S1[(size_t)(r0 + ty + i * 8) * DHh + c0 + tx];
    __syncthreads();
#pragma unroll
    for (int i = 0; i < 4; i++)
        g_S1t[(size_t)(c0 + ty + i * 8) * DAa + r0 + tx] = tile[tx][ty + i * 8];
}

// ---- xw = emb[ids] @ W_ih^T (M=65536, N=1024, K=300), both dirs; skip masked tiles
__global__ void __launch_bounds__(256) k_gemm_xw(const int* __restrict__ ids,
                                                 const float* __restrict__ emb,
                                                 const float* __restrict__ Wf,
                                                 const float* __restrict__ Wb,
                                                 const int* __restrict__ len_li) {
    int m0 = blockIdx.y * 128, n0 = blockIdx.x * 128;
    {
        int b = m0 >> 10, t0 = m0 & 1023;
        if (t0 >= len_li[b]) return;
    }
    const float* Wp = blockIdx.z ? Wb : Wf;
    float* out = blockIdx.z ? g_xw_b : g_xw_f;
    __shared__ __align__(16) float As[8][128];
    __shared__ __align__(16) float Bs[8][128];
    __shared__ int roff[128];
    int tid = threadIdx.x;
    if (tid < 128) roff[tid] = ids[m0 + tid] * Ee;

    unsigned long long acc2[8][4];
#pragma unroll
    for (int i = 0; i < 8; i++)
#pragma unroll
        for (int j = 0; j < 4; j++) acc2[i][j] = 0ULL;

    int mloc = tid >> 1;
    int kloc = (tid & 1) * 4;
    int ty = tid >> 4, tx = tid & 15;
    __syncthreads();

    for (int k0 = 0; k0 < Ee; k0 += 8) {
#pragma unroll
        for (int i = 0; i < 4; i++) {
            int kk = kloc + i, kg = k0 + kk;
            As[kk][mloc] = (kg < Ee) ? emb[(size_t)roff[mloc] + kg] : 0.f;
            Bs[kk][mloc] = (kg < Ee) ? Wp[(size_t)(n0 + mloc) * Ee + kg] : 0.f;
        }
        __syncthreads();
#pragma unroll
        for (int kk = 0; kk < 8; kk++) {
            float a[8];
            *(float4*)&a[0] = *(float4*)&As[kk][ty * 8];
            *(float4*)&a[4] = *(float4*)&As[kk][ty * 8 + 4];
            unsigned long long bp[4];
            const unsigned long long* bsrc = (const unsigned long long*)&Bs[kk][tx * 8];
            bp[0] = bsrc[0]; bp[1] = bsrc[1]; bp[2] = bsrc[2]; bp[3] = bsrc[3];
#pragma unroll
            for (int i = 0; i < 8; i++) {
                unsigned long long ad = pack2(a[i], a[i]);
                ffma2(acc2[i][0], ad, bp[0]);
                ffma2(acc2[i][1], ad, bp[1]);
                ffma2(acc2[i][2], ad, bp[2]);
                ffma2(acc2[i][3], ad, bp[3]);
            }
        }
        __syncthreads();
    }
#pragma unroll
    for (int i = 0; i < 8; i++) {
        float* orow = out + (size_t)(m0 + ty * 8 + i) * Gg + n0 + tx * 8;
        ((ulonglong2*)orow)[0] = make_ulonglong2(acc2[i][0], acc2[i][1]);
        ((ulonglong2*)orow)[1] = make_ulonglong2(acc2[i][2], acc2[i][3]);
    }
}

// ---- LSTM recurrence v4: TWO pipelined 4-batch groups + W in REGISTERS.
// grid (64, 2), cluster (8,1,1), 512 threads.
// Group g = tid>>8 handles batches 4g..4g+3 with its own mbarrier ring; while one
// group waits on its h-exchange, the other group's warps issue their dot.
// Thread (cs 0..63, ks 0..3) owns cols {cs, cs+64}, k-range ks*64..ks*64+63 in regs.
__global__ void __launch_bounds__(512, 1) __cluster_dims__(8, 1, 1)
k_lstm(const float* __restrict__ Whf, const float* __restrict__ Whb,
       const float* __restrict__ h0, const float* __restrict__ c0,
       const int* __restrict__ len_li, float* __restrict__ dout) {
    __shared__ __align__(16) float hb[2][2][4][Hh];       // [g][buf][m][j], 16 KB
    __shared__ float sgb[2][128 * 17];                    // per-group partials
    __shared__ int slen[8];
    __shared__ __align__(8) unsigned long long mbar[4];   // [g*2 + buf]

    int tid = threadIdx.x;
    int dir = blockIdx.y;
    int rank = blockIdx.x & 7;
    int b0 = (blockIdx.x >> 3) * 8;
    int j0 = rank * 32;
    const float* Whh = dir ? Whb : Whf;
    const float* xw  = dir ? g_xw_b : g_xw_f;

    int g = tid >> 8;                 // group 0/1
    int tg = tid & 255;
    int barid = 1 + g;
    float* sg = sgb[g];

    // phase-A mapping
    int cs = tg & 63;
    int ks = tg >> 6;                 // 0..3
    int col0 = cs, col1 = cs + 64;
    int ppbase = ks * 16;
    int gcol0 = (col0 >> 5) * 256 + j0 + (col0 & 31);
    int gcol1 = (col1 >> 5) * 256 + j0 + (col1 & 31);

    // W slices into registers: 2 cols x 16 float4
    ulonglong2 Wr0[16], Wr1[16];
#pragma unroll
    for (int pp = 0; pp < 16; pp++) {
        Wr0[pp] = *(const ulonglong2*)&Whh[(size_t)gcol0 * Hh + (ppbase + pp) * 4];
        Wr1[pp] = *(const ulonglong2*)&Whh[(size_t)gcol1 * Hh + (ppbase + pp) * 4];
    }

    // h0 into buffer 0 of each group
    for (int i = tid; i < 8 * Hh; i += 512) {
        int m = i >> 8, j = i & 255;
        hb[m >> 2][0][m & 3][j] = h0[(size_t)(dir * Bb + b0 + m) * Hh + j];
    }
    if (tid < 8) slen[tid] = len_li[b0 + tid];
    if (tid < 4) mbar_init(smem_u32(&mbar[tid]), 8);
    __syncthreads();
    CLUSTER_SYNC();

    int mlen = max(max(slen[g * 4], slen[g * 4 + 1]),
                   max(slen[g * 4 + 2], slen[g * 4 + 3]));

    // xv ownership: batch ks of this group, cols col0/col1
    int lenx = slen[g * 4 + ks];
    const float* xw0 = xw + ((size_t)(b0 + g * 4 + ks) * Ss) * Gg + gcol0;
    const float* xw1 = xw + ((size_t)(b0 + g * 4 + ks) * Ss) * Gg + gcol1;

    // phase-B: first 128 group threads -> (batch pb 0..3, dim j0+pj)
    bool bact = tg < 128;
    int pb = (tg >> 5) & 3, pj = tg & 31;
    int plen = slen[g * 4 + pb];
    float creg = bact ? c0[(size_t)(dir * Bb + b0 + g * 4 + pb) * Hh + j0 + pj] : 0.f;
    float hreg = bact ? hb[g][0][pb][j0 + pj] : 0.f;
    uint32_t hb_u = smem_u32(&hb[0][0][0][0]);

    // prologue xv for t=0
    float xv0, xv1;
    {
        int p = dir ? lenx - 1 : 0; if (p < 0) p = 0;
        xv0 = __ldg(xw0 + (size_t)p * Gg);
        xv1 = __ldg(xw1 + (size_t)p * Gg);
    }

    int cur = 0;
    int ph0 = 0, ph1 = 0;
    for (int t = 0; t < mlen; t++) {
        // prefetch next xv BEFORE the wait
        float nx0 = 0.f, nx1 = 0.f;
        if (t + 1 < mlen) {
            int p = dir ? lenx - 2 - t : t + 1; if (p < 0) p = 0;
            nx0 = __ldg(xw0 + (size_t)p * Gg);
            nx1 = __ldg(xw1 + (size_t)p * Gg);
        }
        if (t > 0) {
            if (cur == 0) { mbar_waitc(smem_u32(&mbar[g * 2 + 0]), ph0); ph0 ^= 1; }
            else          { mbar_waitc(smem_u32(&mbar[g * 2 + 1]), ph1); ph1 ^= 1; }
        }

        // dot: 2 cols x 4 batches over 64 k, W from registers
        unsigned long long acc0[4] = {0ULL,0ULL,0ULL,0ULL};
        unsigned long long acc1[4] = {0ULL,0ULL,0ULL,0ULL};
        const float* hc = &hb[g][cur][0][ppbase * 4];
#pragma unroll
        for (int pp = 0; pp < 16; pp++) {
            ulonglong2 w0 = Wr0[pp];
            ulonglong2 w1 = Wr1[pp];
#pragma unroll
            for (int m = 0; m < 4; m++) {
                ulonglong2 hv = *(const ulonglong2*)&hc[m * Hh + pp * 4];
                ffma2(acc0[m], w0.x, hv.x); ffma2(acc0[m], w0.y, hv.y);
                ffma2(acc1[m], w1.x, hv.x); ffma2(acc1[m], w1.y, hv.y);
            }
        }
#pragma unroll
        for (int m = 0; m < 4; m++) {
            float p0 = hadd2(acc0[m]);
            float p1 = hadd2(acc1[m]);
            if (m == ks) { p0 += xv0; p1 += xv1; }
            sg[col0 * 17 + ks * 4 + m] = p0;
            sg[col1 * 17 + ks * 4 + m] = p1;
        }
        GROUP_BAR(barid);

        int nxt = cur ^ 1;
        if (bact) {
            int bi = pj * 17 + pb;
            float gi = sg[bi] + sg[bi + 4] + sg[bi + 8] + sg[bi + 12];
            bi = (32 + pj) * 17 + pb;
            float gf = sg[bi] + sg[bi + 4] + sg[bi + 8] + sg[bi + 12];
            bi = (64 + pj) * 17 + pb;
            float gg = sg[bi] + sg[bi + 4] + sg[bi + 8] + sg[bi + 12];
            bi = (96 + pj) * 17 + pb;
            float go = sg[bi] + sg[bi + 4] + sg[bi + 8] + sg[bi + 12];
            if (t < plen) {
                creg = fsig(gf) * creg + fsig(gi) * ftanh(gg);
                hreg = fsig(go) * ftanh(creg);
                int posw = dir ? plen - 1 - t : t;
                g_Hout[((size_t)(b0 + g * 4 + pb) * Ss + posw) * DHh + dir * Hh + j0 + pj] = hreg;
            }
            if (t + 1 < mlen) {
                uint32_t off = hb_u +
                    (uint32_t)(((g * 2 + nxt) * 1024 + pb * Hh + j0 + pj) * 4);
#pragma unroll
                for (int r = 0; r < 8; r++) stc_f32_rank(off, (uint32_t)r, hreg);
            }
        }
        GROUP_BAR(barid);
        if (t + 1 < mlen && tg < 8) {
            FENCE_CLUSTER();
            mbar_arrive_peer(smem_u32(&mbar[g * 2 + nxt]), (uint32_t)tg);
        }
        xv0 = nx0; xv1 = nx1;
        cur = nxt;
    }
    if (bact) {
        dout[H_OFF + (size_t)(dir * Bb + b0 + g * 4 + pb) * Hh + j0 + pj] = hreg;
        dout[C_OFF + (size_t)(dir * Bb + b0 + g * 4 + pb) * Hh + j0 + pj] = creg;
    }
    CLUSTER_SYNC();
}

// ---- s2 = tanh(Hout @ S1^T) @ S2^T, write [b][r][t]; skip masked tiles
__global__ void __launch_bounds__(256) k_s2(const float* __restrict__ S2,
                                            const int* __restrict__ len_li) {
    size_t row0 = (size_t)blockIdx.x * 16;
    int b = (int)(row0 >> 10);
    int t0 = (int)(row0 & 1023);
    if (t0 >= len_li[b]) return;

    __shared__ __align__(16) float Hs[16][DHh];
    __shared__ float t1[16][DAa];
    __shared__ float so[16][17];
    int tid = threadIdx.x;
    for (int idx = tid; idx < 16 * DHh / 4; idx += 256) {
        int r = idx / (DHh / 4);
        int c4 = (idx % (DHh / 4)) * 4;
        *(float4*)&Hs[r][c4] = *(const float4*)&g_Hout[(row0 + r) * DHh + c4];
    }
    __syncthreads();

    int da = tid & 63;
    int rl = tid >> 6;
    float acc[4] = {0.f, 0.f, 0.f, 0.f};
    for (int k = 0; k < DHh; k++) {
        float w = g_S1t[(size_t)k * DAa + da];
        acc[0] = fmaf(w, Hs[rl + 0][k], acc[0]);
        acc[1] = fmaf(w, Hs[rl + 4][k], acc[1]);
        acc[2] = fmaf(w, Hs[rl + 8][k], acc[2]);
        acc[3] = fmaf(w, Hs[rl + 12][k], acc[3]);
    }
    t1[rl + 0][da]  = tanhf(acc[0]);
    t1[rl + 4][da]  = tanhf(acc[1]);
    t1[rl + 8][da]  = tanhf(acc[2]);
    t1[rl + 12][da] = tanhf(acc[3]);
    __syncthreads();

    int row = tid >> 4, rh = tid & 15;
    float s = 0.f;
#pragma unroll 8
    for (int k = 0; k < DAa; k++) s = fmaf(t1[row][k], __ldg(&S2[rh * DAa + k]), s);
    so[row][rh] = s;
    __syncthreads();
    int rr = tid >> 4, tt = tid & 15;
    g_s2[((size_t)b * Rr + rr) * Ss + t0 + tt] = so[tt][rr];
}

// ---- masked softmax over t; A written to dout. grid (R, B)
__global__ void __launch_bounds__(256) k_softmax(const int* __restrict__ len_li,
                                                 float* __restrict__ dout) {
    int r = blockIdx.x, b = blockIdx.y;
    int len = len_li[b];
    int tid = threadIdx.x;
    __shared__ float red[256];
    const float* srow = g_s2 + ((size_t)b * Rr + r) * Ss;
    float* Aout = dout + A_OFF + ((size_t)b * Rr + r) * Ss;

    float m = -1e30f;
    for (int t = tid; t < len; t += 256) m = fmaxf(m, srow[t]);
    red[tid] = m; __syncthreads();
    for (int s = 128; s > 0; s >>= 1) {
        if (tid < s) red[tid] = fmaxf(red[tid], red[tid + s]);
        __syncthreads();
    }
    float M = red[0]; __syncthreads();

    float sum = 0.f;
    for (int t = tid; t < len; t += 256) {
        float e = expf(srow[t] - M);
        Aout[t] = e;
        sum += e;
    }
    red[tid] = sum; __syncthreads();
    for (int s = 128; s > 0; s >>= 1) {
        if (tid < s) red[tid] += red[tid + s];
        __syncthreads();
    }
    float inv = 1.f / red[0];

    for (int t = tid; t < Ss; t += 256)
        Aout[t] = (t < len) ? Aout[t] * inv : 0.f;
}

// ---- BM = A @ Hout. block per b, 512 thr (d)
__global__ void __launch_bounds__(512) k_M(const int* __restrict__ len_li,
                                           const float* __restrict__ dout) {
    int b = blockIdx.x;
    int tid = threadIdx.x;
    int len = len_li[b];
    __shared__ __align__(16) float Asm[128][16];
    float acc[16];
#pragma unroll
    for (int i = 0; i < 16; i++) acc[i] = 0.f;

    const float* Abase = dout + A_OFF + (size_t)b * Rr * Ss;
    for (int tc = 0; tc < len; tc += 128) {
        int nt = min(128, len - tc);
        for (int idx = tid; idx < 16 * 128; idx += 512) {
            int r = idx >> 7, tt = idx & 127;
            Asm[tt][r] = (tt < nt) ? Abase[(size_t)r * Ss + tc + tt] : 0.f;
        }
        __syncthreads();
        for (int tt = 0; tt < nt; tt++) {
            float hv = g_Hout[((size_t)b * Ss + tc + tt) * DHh + tid];
#pragma unroll
            for (int r2 = 0; r2 < 16; r2++)
                acc[r2] = fmaf(Asm[tt][r2], hv, acc[r2]);
        }
        __syncthreads();
    }
#pragma unroll
    for (int r2 = 0; r2 < 16; r2++)
        g_BM[(size_t)b * RKk + r2 * DHh + tid] = acc[r2];
}

// ---- AAT penal partial. block per b, thread (r,q)
__global__ void __launch_bounds__(256) k_aat(const int* __restrict__ len_li,
                                             const float* __restrict__ dout) {
    int b = blockIdx.x;
    int tid = threadIdx.x;
    int r = tid >> 4, q = tid & 15;
    int len = len_li[b];
    const float* Abase = dout + A_OFF + (size_t)b * Rr * Ss;
    __shared__ float As2[16][257];
    float s = 0.f;
    for (int tc = 0; tc < len; tc += 256) {
        int nt = min(256, len - tc);
        for (int i = tid; i < 16 * 256; i += 256) {
            int rr = i >> 8, tt = i & 255;
            As2[rr][tt] = (tt < nt) ? Abase[(size_t)rr * Ss + tc + tt] : 0.f;
        }
        __syncthreads();
#pragma unroll 4
        for (int tt = 0; tt < 256; tt++)
            s = fmaf(As2[r][tt], As2[q][tt], s);
        __syncthreads();
    }
    float d = s - (r == q ? 1.f : 0.f);
    __shared__ float red[256];
    red[tid] = d * d; __syncthreads();
    for (int st = 128; st > 0; st >>= 1) {
        if (tid < st) red[tid] += red[tid + st];
        __syncthreads();
    }
    if (tid == 0) g_pp[b] = red[0];
}

__global__ void k_pen(float* __restrict__ dout) {
    __shared__ float red[64];
    int tid = threadIdx.x;
    red[tid] = g_pp[tid]; __syncthreads();
    for (int st = 32; st > 0; st >>= 1) {
        if (tid < st) red[tid] += red[tid + st];
        __syncthreads();
    }
    if (tid == 0) dout[PEN_OFF] = red[0] / 64.f;
}

// ---- hid = relu(BM @ W^T + b): tiled GEMM, 96 blocks
__global__ void __launch_bounds__(256) k_hid(const float* __restrict__ Wet,  const float* __restrict__ bet,
                                             const float* __restrict__ Wprt, const float* __restrict__ bprt,
                                             const float* __restrict__ Wpop, const float* __restrict__ bpop) {
    int blk = blockIdx.x;
    int head = blk >> 5;
    int j0 = (blk & 31) * 16;
    const float* W    = (head == 0) ? Wet : (head == 1) ? Wprt : Wpop;
    const float* bias = (head == 0) ? bet : (head == 1) ? bprt : bpop;
    __shared__ float Ws[16][64];
    __shared__ float Bs[64][65];
    int tid = threadIdx.x;
    int rj = tid >> 4;
    int bq = (tid & 15) * 4;
    float acc[4] = {0.f, 0.f, 0.f, 0.f};
    for (int kc = 0; kc < RKk; kc += 64) {
        for (int i = tid; i < 1024; i += 256) {
            int r = i >> 6, k = i & 63;
            Ws[r][k] = W[(size_t)(j0 + r) * RKk + kc + k];
        }
        for (int i = tid; i < 4096; i += 256) {
            int bx = i >> 6, k = i & 63;
            Bs[bx][k] = g_BM[(size_t)bx * RKk + kc + k];
        }
        __syncthreads();
#pragma unroll 4
        for (int k = 0; k < 64; k++) {
            float w = Ws[rj][k];
            acc[0] = fmaf(w, Bs[bq + 0][k], acc[0]);
            acc[1] = fmaf(w, Bs[bq + 1][k], acc[1]);
            acc[2] = fmaf(w, Bs[bq + 2][k], acc[2]);
            acc[3] = fmaf(w, Bs[bq + 3][k], acc[3]);
        }
        __syncthreads();
    }
    float bv = bias[j0 + rj];
#pragma unroll
    for (int q = 0; q < 4; q++)
        g_hid[((size_t)head * Bb + bq + q) * MHh + j0 + rj] = fmaxf(acc[q] + bv, 0.f);
}

// ---- decode: grid (B, 3), 64 threads
__global__ void __launch_bounds__(64) k_dec(const float* __restrict__ Wdet,  const float* __restrict__ bdet,
                                            const float* __restrict__ Wdprt, const float* __restrict__ bdprt,
                                            const float* __restrict__ Wdpop, const float* __restrict__ bdpop,
                                            float* __restrict__ dout) {
    int b = blockIdx.x, head = blockIdx.y;
    int tid = threadIdx.x;
    const float* Wd; const float* bd; int N; int off;
    if (head == 0)      { Wd = Wdet;  bd = bdet;  N = 50; off = ET_OFF;   }
    else if (head == 1) { Wd = Wdprt; bd = bdprt; N = 12; off = PRT_OFF;  }
    else                { Wd = Wdpop; bd = bdpop; N = 8;  off = POPT_OFF; }
    __shared__ float sh[MHh];
    for (int k = tid; k < MHh; k += 64)
        sh[k] = g_hid[((size_t)head * Bb + b) * MHh + k];
    __syncthreads();
    if (tid < N) {
        float s = bd[tid];
        const float* wr = Wd + (size_t)tid * MHh;
        for (int k = 0; k < MHh; k++) s = fmaf(sh[k], wr[k], s);
        dout[off + b * N + tid] = s;
    }
}

extern "C" void kernel_launch(void* const* d_in, const int* in_sizes, int n_in,
                              void* d_out, int out_size) {
    const int*   ids   = (const int*)d_in[0];
    const int*   lens  = (const int*)d_in[1];
    const float* h0    = (const float*)d_in[2];
    const float* c0    = (const float*)d_in[3];
    const float* emb   = (const float*)d_in[4];
    const float* Wihf  = (const float*)d_in[5];
    const float* Whhf  = (const float*)d_in[6];
    const float* Wihb  = (const float*)d_in[7];
    const float* Whhb  = (const float*)d_in[8];
    const float* S1    = (const float*)d_in[9];
    const float* S2    = (const float*)d_in[10];
    const float* Wet   = (const float*)d_in[11];
    const float* bet   = (const float*)d_in[12];
    const float* Wdet  = (const float*)d_in[13];
    const float* bdet  = (const float*)d_in[14];
    const float* Wprt  = (const float*)d_in[15];
    const float* bprt  = (const float*)d_in[16];
    const float* Wdprt = (const float*)d_in[17];
    const float* bdprt = (const float*)d_in[18];
    const float* Wpop  = (const float*)d_in[19];
    const float* bpop  = (const float*)d_in[20];
    const float* Wdpop = (const float*)d_in[21];
    const float* bdpop = (const float*)d_in[22];
    float* dout = (float*)d_out;

    k_transpose<<<dim3(16, 2), dim3(32, 8)>>>(S1);
    k_gemm_xw<<<dim3(8, 512, 2), 256>>>(ids, emb, Wihf, Wihb, lens);
    k_noop<<<1, 32>>>();   // aligns ncu's captured slot (4th launch) onto k_lstm
    k_lstm<<<dim3(64, 2), 512>>>(Whhf, Whhb, h0, c0, lens, dout);
    k_s2<<<4096, 256>>>(S2, lens);
    k_softmax<<<dim3(Rr, Bb), 256>>>(lens, dout);
    k_M<<<Bb, 512>>>(lens, dout);
    k_aat<<<Bb, 256>>>(lens, dout);
    k_pen<<<1, 64>>>(dout);
    k_hid<<<96, 256>>>(Wet, bet, Wprt, bprt, Wpop, bpop);
    k_dec<<<dim3(Bb, 3), 64>>>(Wdet, bdet, Wdprt, bdprt, Wdpop, bdpop, dout);
}

// round 17
// speedup vs baseline: 1.4317x; 1.4317x over previous
#include <cuda_runtime.h>
#include <math.h>
#include <stdint.h>

#define Bb 64
#define Ss 1024
#define Ee 300
#define Hh 256
#define Gg 1024
#define DHh 512
#define DAa 64
#define Rr 16
#define MHh 512
#define RKk 8192

#define ET_OFF   0
#define PRT_OFF  3200
#define POPT_OFF 3968
#define H_OFF    4480
#define C_OFF    37248
#define PEN_OFF  70016
#define A_OFF    70017

__device__ float g_xw_f[Bb * Ss * Gg];
__device__ float g_xw_b[Bb * Ss * Gg];
__device__ float g_S1t[DHh * DAa];
__device__ float g_Hout[Bb * Ss * DHh];
__device__ float g_s2[Bb * Rr * Ss];   // [b][r][t]
__device__ float g_BM[Bb * RKk];
__device__ float g_hid[3 * Bb * MHh];
__device__ float g_pp[Bb];

__device__ __forceinline__ float fsig(float x) {
    return __fdividef(1.f, 1.f + __expf(-x));
}
__device__ __forceinline__ float ftanh(float x) {
    return 1.f - __fdividef(2.f, __expf(2.f * x) + 1.f);
}
__device__ __forceinline__ void ffma2(unsigned long long& d, unsigned long long a,
                                      unsigned long long b) {
    asm("fma.rn.f32x2 %0, %1, %2, %0;" : "+l"(d) : "l"(a), "l"(b));
}
__device__ __forceinline__ unsigned long long pack2(float x, float y) {
    unsigned long long r;
    asm("mov.b64 %0, {%1, %2};" : "=l"(r) : "r"(__float_as_uint(x)), "r"(__float_as_uint(y)));
    return r;
}
__device__ __forceinline__ float hadd2(unsigned long long v) {
    union { unsigned long long u; float2 f; } cv;
    cv.u = v;
    return cv.f.x + cv.f.y;
}
__device__ __forceinline__ uint32_t smem_u32(const void* p) {
    return (uint32_t)__cvta_generic_to_shared(p);
}
__device__ __forceinline__ uint32_t mapa_u32(uint32_t a, uint32_t r) {
    uint32_t o;
    asm("mapa.shared::cluster.u32 %0, %1, %2;" : "=r"(o) : "r"(a), "r"(r));
    return o;
}
__device__ __forceinline__ void mbar_init(uint32_t a, uint32_t cnt) {
    asm volatile("mbarrier.init.shared.b64 [%0], %1;" :: "r"(a), "r"(cnt) : "memory");
}
__device__ __forceinline__ void mbar_expect_tx(uint32_t a, uint32_t bytes) {
    asm volatile("mbarrier.arrive.expect_tx.shared.b64 _, [%0], %1;"
                 :: "r"(a), "r"(bytes) : "memory");
}
// transaction-tracked remote store: bytes complete on the DESTINATION CTA's mbarrier
__device__ __forceinline__ void st_async_u32(uint32_t raddr, uint32_t rmbar, uint32_t v) {
    asm volatile("st.async.shared::cluster.mbarrier::complete_tx::bytes.u32 [%0], %1, [%2];"
                 :: "r"(raddr), "r"(v), "r"(rmbar) : "memory");
}
__device__ __forceinline__ void mbar_waitc(uint32_t addr, uint32_t parity) {
    uint32_t done;
    do {
        asm volatile(
            "{\n\t.reg .pred p;\n\t"
            "mbarrier.try_wait.parity.acquire.cluster.shared::cta.b64 p, [%1], %2;\n\t"
            "selp.b32 %0, 1, 0, p;\n\t}"
            : "=r"(done) : "r"(addr), "r"(parity) : "memory");
    } while (!done);
}
#define GROUP_BAR(id) asm volatile("bar.sync %0, %1;" :: "r"(id), "r"(256) : "memory")
#define CLUSTER_SYNC() do { \
    asm volatile("barrier.cluster.arrive.aligned;" ::: "memory"); \
    asm volatile("barrier.cluster.wait.aligned;" ::: "memory"); \
} while (0)

// ---- no-op launch to align ncu's captured slot onto k_lstm
__global__ void k_noop() {
    if (threadIdx.x == 1024) g_pp[0] = 0.f;   // never true
}

// ---- S1 transpose only (64x512 -> 512x64)
__global__ void k_transpose(const float* __restrict__ S1) {
    int c0 = blockIdx.x * 32, r0 = blockIdx.y * 32;
    __shared__ float tile[32][33];
    int tx = threadIdx.x, ty = threadIdx.y;
#pragma unroll
    for (int i = 0; i < 4; i++)
        tile[ty + i * 8][tx] = S1[(size_t)(r0 + ty + i * 8) * DHh + c0 + tx];
    __syncthreads();
#pragma unroll
    for (int i = 0; i < 4; i++)
        g_S1t[(size_t)(c0 + ty + i * 8) * DAa + r0 + tx] = tile[tx][ty + i * 8];
}

// ---- xw = emb[ids] @ W_ih^T (M=65536, N=1024, K=300), both dirs; skip masked tiles
__global__ void __launch_bounds__(256) k_gemm_xw(const int* __restrict__ ids,
                                                 const float* __restrict__ emb,
                                                 const float* __restrict__ Wf,
                                                 const float* __restrict__ Wb,
                                                 const int* __restrict__ len_li) {
    int m0 = blockIdx.y * 128, n0 = blockIdx.x * 128;
    {
        int b = m0 >> 10, t0 = m0 & 1023;
        if (t0 >= len_li[b]) return;
    }
    const float* Wp = blockIdx.z ? Wb : Wf;
    float* out = blockIdx.z ? g_xw_b : g_xw_f;
    __shared__ __align__(16) float As[8][128];
    __shared__ __align__(16) float Bs[8][128];
    __shared__ int roff[128];
    int tid = threadIdx.x;
    if (tid < 128) roff[tid] = ids[m0 + tid] * Ee;

    unsigned long long acc2[8][4];
#pragma unroll
    for (int i = 0; i < 8; i++)
#pragma unroll
        for (int j = 0; j < 4; j++) acc2[i][j] = 0ULL;

    int mloc = tid >> 1;
    int kloc = (tid & 1) * 4;
    int ty = tid >> 4, tx = tid & 15;
    __syncthreads();

    for (int k0 = 0; k0 < Ee; k0 += 8) {
#pragma unroll
        for (int i = 0; i < 4; i++) {
            int kk = kloc + i, kg = k0 + kk;
            As[kk][mloc] = (kg < Ee) ? emb[(size_t)roff[mloc] + kg] : 0.f;
            Bs[kk][mloc] = (kg < Ee) ? Wp[(size_t)(n0 + mloc) * Ee + kg] : 0.f;
        }
        __syncthreads();
#pragma unroll
        for (int kk = 0; kk < 8; kk++) {
            float a[8];
            *(float4*)&a[0] = *(float4*)&As[kk][ty * 8];
            *(float4*)&a[4] = *(float4*)&As[kk][ty * 8 + 4];
            unsigned long long bp[4];
            const unsigned long long* bsrc = (const unsigned long long*)&Bs[kk][tx * 8];
            bp[0] = bsrc[0]; bp[1] = bsrc[1]; bp[2] = bsrc[2]; bp[3] = bsrc[3];
#pragma unroll
            for (int i = 0; i < 8; i++) {
                unsigned long long ad = pack2(a[i], a[i]);
                ffma2(acc2[i][0], ad, bp[0]);
                ffma2(acc2[i][1], ad, bp[1]);
                ffma2(acc2[i][2], ad, bp[2]);
                ffma2(acc2[i][3], ad, bp[3]);
            }
        }
        __syncthreads();
    }
#pragma unroll
    for (int i = 0; i < 8; i++) {
        float* orow = out + (size_t)(m0 + ty * 8 + i) * Gg + n0 + tx * 8;
        ((ulonglong2*)orow)[0] = make_ulonglong2(acc2[i][0], acc2[i][1]);
        ((ulonglong2*)orow)[1] = make_ulonglong2(acc2[i][2], acc2[i][3]);
    }
}

// ---- LSTM recurrence v5: two pipelined 4-batch groups, W in smem,
// h exchange via st.async (tx-tracked) -> NO fence, NO remote arrives.
// grid (64, 2), cluster (8,1,1), 512 threads.
// dyn smem floats: Wv 32768 | hb [g][buf][m][256] = 4096 | sgb [g][tb][128*17] = 8704
#define LSTM_SMEM_FLOATS (32768 + 4096 + 8704)
__global__ void __launch_bounds__(512, 1) __cluster_dims__(8, 1, 1)
k_lstm(const float* __restrict__ Whf, const float* __restrict__ Whb,
       const float* __restrict__ h0, const float* __restrict__ c0,
       const int* __restrict__ len_li, float* __restrict__ dout) {
    extern __shared__ float smem[];
    float4* Wv = (float4*)smem;              // [pp(64)][cc(128)]
    float* hb  = smem + 32768;               // [(g*2+buf)*1024 + m*256 + j]
    float* sgb = smem + 32768 + 4096;        // [(g*2+tb)*2176 + cc*17 + ks*4 + m]
    __shared__ int slen[8];
    __shared__ __align__(8) unsigned long long mbar[4];   // [g*2 + buf]

    int tid = threadIdx.x;
    int dir = blockIdx.y;
    int rank = blockIdx.x & 7;
    int b0 = (blockIdx.x >> 3) * 8;
    int j0 = rank * 32;
    const float* Whh = dir ? Whb : Whf;
    const float* xw  = dir ? g_xw_b : g_xw_f;

    // W slice for this CTA's 128 gate columns
    for (int i = tid; i < 128 * 64; i += 512) {
        int cc = i >> 6, pp = i & 63;
        int gcol = (cc >> 5) * 256 + j0 + (cc & 31);
        Wv[pp * 128 + cc] = *(const float4*)&Whh[(size_t)gcol * Hh + pp * 4];
    }
    // h0 into buffer 0 of each group
    for (int i = tid; i < 8 * Hh; i += 512) {
        int m = i >> 8, j = i & 255;
        hb[(m >> 2) * 2048 + (m & 3) * 256 + j] = h0[(size_t)(dir * Bb + b0 + m) * Hh + j];
    }
    if (tid < 8) slen[tid] = len_li[b0 + tid];
    if (tid < 4) mbar_init(smem_u32(&mbar[tid]), 1);   // 1 arrival = the local armer
    __syncthreads();
    CLUSTER_SYNC();

    int g = tid >> 8;                 // group 0/1
    int tg = tid & 255;
    int barid = 1 + g;
    int mlen = max(max(slen[g * 4], slen[g * 4 + 1]),
                   max(slen[g * 4 + 2], slen[g * 4 + 3]));

    // phase-A mapping: cs 0..63 (cols {cs, cs+64}), ks 0..3 (16 float4 k-chunks)
    int cs = tg & 63;
    int ks = tg >> 6;
    int col0 = cs, col1 = cs + 64;
    int ppbase = ks * 16;
    int gcol0 = (col0 >> 5) * 256 + j0 + (col0 & 31);
    int gcol1 = (col1 >> 5) * 256 + j0 + (col1 & 31);
    int lenx = slen[g * 4 + ks];
    const float* xw0 = xw + ((size_t)(b0 + g * 4 + ks) * Ss) * Gg + gcol0;
    const float* xw1 = xw + ((size_t)(b0 + g * 4 + ks) * Ss) * Gg + gcol1;
    const ulonglong2* Wu = (const ulonglong2*)Wv;

    // phase-B mapping: first 128 group threads -> (batch pb 0..3, dim j0+pj)
    bool bact = tg < 128;
    int pb = (tg >> 5) & 3, pj = tg & 31;
    int plen = slen[g * 4 + pb];
    float creg = bact ? c0[(size_t)(dir * Bb + b0 + g * 4 + pb) * Hh + j0 + pj] : 0.f;
    float hreg = bact ? hb[g * 2048 + pb * 256 + j0 + pj] : 0.f;

    // cluster-peer base addresses (mapa is window-linear: peer addr = pbase[r] + rel)
    uint32_t base0 = smem_u32(smem);
    uint32_t pbase[8];
#pragma unroll
    for (int r = 0; r < 8; r++) pbase[r] = mapa_u32(base0, r);
    uint32_t mrel0 = smem_u32(&mbar[g * 2 + 0]) - base0;
    uint32_t mrel1 = smem_u32(&mbar[g * 2 + 1]) - base0;
    uint32_t hrel  = (uint32_t)((32768 + g * 2048 + pb * 256 + j0 + pj) * 4);

    // prologue xv for t=0
    float xv0, xv1;
    {
        int p = dir ? lenx - 1 : 0; if (p < 0) p = 0;
        xv0 = __ldg(xw0 + (size_t)p * Gg);
        xv1 = __ldg(xw1 + (size_t)p * Gg);
    }

    int cur = 0;
    int ph0 = 0, ph1 = 0;
    for (int t = 0; t < mlen; t++) {
        // prefetch next xv BEFORE the wait
        float nx0 = 0.f, nx1 = 0.f;
        if (t + 1 < mlen) {
            int p = dir ? lenx - 2 - t : t + 1; if (p < 0) p = 0;
            nx0 = __ldg(xw0 + (size_t)p * Gg);
            nx1 = __ldg(xw1 + (size_t)p * Gg);
        }
        if (t > 0) {
            if (cur == 0) { mbar_waitc(smem_u32(&mbar[g * 2 + 0]), ph0); ph0 ^= 1; }
            else          { mbar_waitc(smem_u32(&mbar[g * 2 + 1]), ph1); ph1 ^= 1; }
        }
        int nxt = cur ^ 1;
        // arm own barrier for this step's production (4096 bytes from 8 producers)
        if (t + 1 < mlen && tg == 0)
            mbar_expect_tx(smem_u32(&mbar[g * 2 + nxt]), 4096);

        // dot: 2 cols x 4 batches over 64 k, W from smem
        unsigned long long acc0[4] = {0ULL,0ULL,0ULL,0ULL};
        unsigned long long acc1[4] = {0ULL,0ULL,0ULL,0ULL};
        const float* hc = &hb[(g * 2 + cur) * 1024 + ppbase * 4];
        float* sg = sgb + (size_t)(g * 2 + (t & 1)) * 2176;
#pragma unroll
        for (int pp = 0; pp < 16; pp++) {
            ulonglong2 w0 = Wu[(ppbase + pp) * 128 + col0];
            ulonglong2 w1 = Wu[(ppbase + pp) * 128 + col1];
#pragma unroll
            for (int m = 0; m < 4; m++) {
                ulonglong2 hv = *(const ulonglong2*)&hc[m * 256 + pp * 4];
                ffma2(acc0[m], w0.x, hv.x); ffma2(acc0[m], w0.y, hv.y);
                ffma2(acc1[m], w1.x, hv.x); ffma2(acc1[m], w1.y, hv.y);
            }
        }
#pragma unroll
        for (int m = 0; m < 4; m++) {
            float p0 = hadd2(acc0[m]);
            float p1 = hadd2(acc1[m]);
            if (m == ks) { p0 += xv0; p1 += xv1; }
            sg[col0 * 17 + ks * 4 + m] = p0;
            sg[col1 * 17 + ks * 4 + m] = p1;
        }
        GROUP_BAR(barid);

        if (bact) {
            int bi = pj * 17 + pb;
            float gi = sg[bi] + sg[bi + 4] + sg[bi + 8] + sg[bi + 12];
            bi = (32 + pj) * 17 + pb;
            float gf = sg[bi] + sg[bi + 4] + sg[bi + 8] + sg[bi + 12];
            bi = (64 + pj) * 17 + pb;
            float gg = sg[bi] + sg[bi + 4] + sg[bi + 8] + sg[bi + 12];
            bi = (96 + pj) * 17 + pb;
            float go = sg[bi] + sg[bi + 4] + sg[bi + 8] + sg[bi + 12];
            if (t < plen) {
                creg = fsig(gf) * creg + fsig(gi) * ftanh(gg);
                hreg = fsig(go) * ftanh(creg);
            }
            if (t + 1 < mlen) {
                uint32_t orel = hrel + (uint32_t)(nxt * 4096);
                uint32_t mrel = nxt ? mrel1 : mrel0;
                uint32_t hv = __float_as_uint(hreg);
#pragma unroll
                for (int r = 0; r < 8; r++)
                    st_async_u32(pbase[r] + orel, pbase[r] + mrel, hv);
            }
            if (t < plen) {
                int posw = dir ? plen - 1 - t : t;
                g_Hout[((size_t)(b0 + g * 4 + pb) * Ss + posw) * DHh + dir * Hh + j0 + pj] = hreg;
            }
        }
        xv0 = nx0; xv1 = nx1;
        cur = nxt;
    }
    if (bact) {
        dout[H_OFF + (size_t)(dir * Bb + b0 + g * 4 + pb) * Hh + j0 + pj] = hreg;
        dout[C_OFF + (size_t)(dir * Bb + b0 + g * 4 + pb) * Hh + j0 + pj] = creg;
    }
    CLUSTER_SYNC();
}

// ---- s2 = tanh(Hout @ S1^T) @ S2^T, write [b][r][t]; skip masked tiles
__global__ void __launch_bounds__(256) k_s2(const float* __restrict__ S2,
                                            const int* __restrict__ len_li) {
    size_t row0 = (size_t)blockIdx.x * 16;
    int b = (int)(row0 >> 10);
    int t0 = (int)(row0 & 1023);
    if (t0 >= len_li[b]) return;

    __shared__ __align__(16) float Hs[16][DHh];
    __shared__ float t1[16][DAa];
    __shared__ float so[16][17];
    int tid = threadIdx.x;
    for (int idx = tid; idx < 16 * DHh / 4; idx += 256) {
        int r = idx / (DHh / 4);
        int c4 = (idx % (DHh / 4)) * 4;
        *(float4*)&Hs[r][c4] = *(const float4*)&g_Hout[(row0 + r) * DHh + c4];
    }
    __syncthreads();

    int da = tid & 63;
    int rl = tid >> 6;
    float acc[4] = {0.f, 0.f, 0.f, 0.f};
    for (int k = 0; k < DHh; k++) {
        float w = g_S1t[(size_t)k * DAa + da];
        acc[0] = fmaf(w, Hs[rl + 0][k], acc[0]);
        acc[1] = fmaf(w, Hs[rl + 4][k], acc[1]);
        acc[2] = fmaf(w, Hs[rl + 8][k], acc[2]);
        acc[3] = fmaf(w, Hs[rl + 12][k], acc[3]);
    }
    t1[rl + 0][da]  = tanhf(acc[0]);
    t1[rl + 4][da]  = tanhf(acc[1]);
    t1[rl + 8][da]  = tanhf(acc[2]);
    t1[rl + 12][da] = tanhf(acc[3]);
    __syncthreads();

    int row = tid >> 4, rh = tid & 15;
    float s = 0.f;
#pragma unroll 8
    for (int k = 0; k < DAa; k++) s = fmaf(t1[row][k], __ldg(&S2[rh * DAa + k]), s);
    so[row][rh] = s;
    __syncthreads();
    int rr = tid >> 4, tt = tid & 15;
    g_s2[((size_t)b * Rr + rr) * Ss + t0 + tt] = so[tt][rr];
}

// ---- masked softmax over t; A written to dout. grid (R, B)
__global__ void __launch_bounds__(256) k_softmax(const int* __restrict__ len_li,
                                                 float* __restrict__ dout) {
    int r = blockIdx.x, b = blockIdx.y;
    int len = len_li[b];
    int tid = threadIdx.x;
    __shared__ float red[256];
    const float* srow = g_s2 + ((size_t)b * Rr + r) * Ss;
    float* Aout = dout + A_OFF + ((size_t)b * Rr + r) * Ss;

    float m = -1e30f;
    for (int t = tid; t < len; t += 256) m = fmaxf(m, srow[t]);
    red[tid] = m; __syncthreads();
    for (int s = 128; s > 0; s >>= 1) {
        if (tid < s) red[tid] = fmaxf(red[tid], red[tid + s]);
        __syncthreads();
    }
    float M = red[0]; __syncthreads();

    float sum = 0.f;
    for (int t = tid; t < len; t += 256) {
        float e = expf(srow[t] - M);
        Aout[t] = e;
        sum += e;
    }
    red[tid] = sum; __syncthreads();
    for (int s = 128; s > 0; s >>= 1) {
        if (tid < s) red[tid] += red[tid + s];
        __syncthreads();
    }
    float inv = 1.f / red[0];

    for (int t = tid; t < Ss; t += 256)
        Aout[t] = (t < len) ? Aout[t] * inv : 0.f;
}

// ---- BM = A @ Hout. block per b, 512 thr (d)
__global__ void __launch_bounds__(512) k_M(const int* __restrict__ len_li,
                                           const float* __restrict__ dout) {
    int b = blockIdx.x;
    int tid = threadIdx.x;
    int len = len_li[b];
    __shared__ __align__(16) float Asm[128][16];
    float acc[16];
#pragma unroll
    for (int i = 0; i < 16; i++) acc[i] = 0.f;

    const float* Abase = dout + A_OFF + (size_t)b * Rr * Ss;
    for (int tc = 0; tc < len; tc += 128) {
        int nt = min(128, len - tc);
        for (int idx = tid; idx < 16 * 128; idx += 512) {
            int r = idx >> 7, tt = idx & 127;
            Asm[tt][r] = (tt < nt) ? Abase[(size_t)r * Ss + tc + tt] : 0.f;
        }
        __syncthreads();
        for (int tt = 0; tt < nt; tt++) {
            float hv = g_Hout[((size_t)b * Ss + tc + tt) * DHh + tid];
#pragma unroll
            for (int r2 = 0; r2 < 16; r2++)
                acc[r2] = fmaf(Asm[tt][r2], hv, acc[r2]);
        }
        __syncthreads();
    }
#pragma unroll
    for (int r2 = 0; r2 < 16; r2++)
        g_BM[(size_t)b * RKk + r2 * DHh + tid] = acc[r2];
}

// ---- AAT penal partial. block per b, thread (r,q)
__global__ void __launch_bounds__(256) k_aat(const int* __restrict__ len_li,
                                             const float* __restrict__ dout) {
    int b = blockIdx.x;
    int tid = threadIdx.x;
    int r = tid >> 4, q = tid & 15;
    int len = len_li[b];
    const float* Abase = dout + A_OFF + (size_t)b * Rr * Ss;
    __shared__ float As2[16][257];
    float s = 0.f;
    for (int tc = 0; tc < len; tc += 256) {
        int nt = min(256, len - tc);
        for (int i = tid; i < 16 * 256; i += 256) {
            int rr = i >> 8, tt = i & 255;
            As2[rr][tt] = (tt < nt) ? Abase[(size_t)rr * Ss + tc + tt] : 0.f;
        }
        __syncthreads();
#pragma unroll 4
        for (int tt = 0; tt < 256; tt++)
            s = fmaf(As2[r][tt], As2[q][tt], s);
        __syncthreads();
    }
    float d = s - (r == q ? 1.f : 0.f);
    __shared__ float red[256];
    red[tid] = d * d; __syncthreads();
    for (int st = 128; st > 0; st >>= 1) {
        if (tid < st) red[tid] += red[tid + st];
        __syncthreads();
    }
    if (tid == 0) g_pp[b] = red[0];
}

__global__ void k_pen(float* __restrict__ dout) {
    __shared__ float red[64];
    int tid = threadIdx.x;
    red[tid] = g_pp[tid]; __syncthreads();
    for (int st = 32; st > 0; st >>= 1) {
        if (tid < st) red[tid] += red[tid + st];
        __syncthreads();
    }
    if (tid == 0) dout[PEN_OFF] = red[0] / 64.f;
}

// ---- hid = relu(BM @ W^T + b): tiled GEMM, 96 blocks
__global__ void __launch_bounds__(256) k_hid(const float* __restrict__ Wet,  const float* __restrict__ bet,
                                             const float* __restrict__ Wprt, const float* __restrict__ bprt,
                                             const float* __restrict__ Wpop, const float* __restrict__ bpop) {
    int blk = blockIdx.x;
    int head = blk >> 5;
    int j0 = (blk & 31) * 16;
    const float* W    = (head == 0) ? Wet : (head == 1) ? Wprt : Wpop;
    const float* bias = (head == 0) ? bet : (head == 1) ? bprt : bpop;
    __shared__ float Ws[16][64];
    __shared__ float Bs[64][65];
    int tid = threadIdx.x;
    int rj = tid >> 4;
    int bq = (tid & 15) * 4;
    float acc[4] = {0.f, 0.f, 0.f, 0.f};
    for (int kc = 0; kc < RKk; kc += 64) {
        for (int i = tid; i < 1024; i += 256) {
            int r = i >> 6, k = i & 63;
            Ws[r][k] = W[(size_t)(j0 + r) * RKk + kc + k];
        }
        for (int i = tid; i < 4096; i += 256) {
            int bx = i >> 6, k = i & 63;
            Bs[bx][k] = g_BM[(size_t)bx * RKk + kc + k];
        }
        __syncthreads();
#pragma unroll 4
        for (int k = 0; k < 64; k++) {
            float w = Ws[rj][k];
            acc[0] = fmaf(w, Bs[bq + 0][k], acc[0]);
            acc[1] = fmaf(w, Bs[bq + 1][k], acc[1]);
            acc[2] = fmaf(w, Bs[bq + 2][k], acc[2]);
            acc[3] = fmaf(w, Bs[bq + 3][k], acc[3]);
        }
        __syncthreads();
    }
    float bv = bias[j0 + rj];
#pragma unroll
    for (int q = 0; q < 4; q++)
        g_hid[((size_t)head * Bb + bq + q) * MHh + j0 + rj] = fmaxf(acc[q] + bv, 0.f);
}

// ---- decode: grid (B, 3), 64 threads
__global__ void __launch_bounds__(64) k_dec(const float* __restrict__ Wdet,  const float* __restrict__ bdet,
                                            const float* __restrict__ Wdprt, const float* __restrict__ bdprt,
                                            const float* __restrict__ Wdpop, const float* __restrict__ bdpop,
                                            float* __restrict__ dout) {
    int b = blockIdx.x, head = blockIdx.y;
    int tid = threadIdx.x;
    const float* Wd; const float* bd; int N; int off;
    if (head == 0)      { Wd = Wdet;  bd = bdet;  N = 50; off = ET_OFF;   }
    else if (head == 1) { Wd = Wdprt; bd = bdprt; N = 12; off = PRT_OFF;  }
    else                { Wd = Wdpop; bd = bdpop; N = 8;  off = POPT_OFF; }
    __shared__ float sh[MHh];
    for (int k = tid; k < MHh; k += 64)
        sh[k] = g_hid[((size_t)head * Bb + b) * MHh + k];
    __syncthreads();
    if (tid < N) {
        float s = bd[tid];
        const float* wr = Wd + (size_t)tid * MHh;
        for (int k = 0; k < MHh; k++) s = fmaf(sh[k], wr[k], s);
        dout[off + b * N + tid] = s;
    }
}

extern "C" void kernel_launch(void* const* d_in, const int* in_sizes, int n_in,
                              void* d_out, int out_size) {
    const int*   ids   = (const int*)d_in[0];
    const int*   lens  = (const int*)d_in[1];
    const float* h0    = (const float*)d_in[2];
    const float* c0    = (const float*)d_in[3];
    const float* emb   = (const float*)d_in[4];
    const float* Wihf  = (const float*)d_in[5];
    const float* Whhf  = (const float*)d_in[6];
    const float* Wihb  = (const float*)d_in[7];
    const float* Whhb  = (const float*)d_in[8];
    const float* S1    = (const float*)d_in[9];
    const float* S2    = (const float*)d_in[10];
    const float* Wet   = (const float*)d_in[11];
    const float* bet   = (const float*)d_in[12];
    const float* Wdet  = (const float*)d_in[13];
    const float* bdet  = (const float*)d_in[14];
    const float* Wprt  = (const float*)d_in[15];
    const float* bprt  = (const float*)d_in[16];
    const float* Wdprt = (const float*)d_in[17];
    const float* bdprt = (const float*)d_in[18];
    const float* Wpop  = (const float*)d_in[19];
    const float* bpop  = (const float*)d_in[20];
    const float* Wdpop = (const float*)d_in[21];
    const float* bdpop = (const float*)d_in[22];
    float* dout = (float*)d_out;

    static int smem_set = 0;
    if (!smem_set) {
        cudaFuncSetAttribute(k_lstm, cudaFuncAttributeMaxDynamicSharedMemorySize,
                             LSTM_SMEM_FLOATS * 4);
        smem_set = 1;
    }

    k_transpose<<<dim3(16, 2), dim3(32, 8)>>>(S1);
    k_gemm_xw<<<dim3(8, 512, 2), 256>>>(ids, emb, Wihf, Wihb, lens);
    k_noop<<<1, 32>>>();   // keeps ncu's captured slot on k_lstm
    k_lstm<<<dim3(64, 2), 512, LSTM_SMEM_FLOATS * 4>>>(Whhf, Whhb, h0, c0, lens, dout);
    k_s2<<<4096, 256>>>(S2, lens);
    k_softmax<<<dim3(Rr, Bb), 256>>>(lens, dout);
    k_M<<<Bb, 512>>>(lens, dout);
    k_aat<<<Bb, 256>>>(lens, dout);
    k_pen<<<1, 64>>>(dout);
    k_hid<<<96, 256>>>(Wet, bet, Wprt, bprt, Wpop, bpop);
    k_dec<<<dim3(Bb, 3), 64>>>(Wdet, bdet, Wdprt, bdprt, Wdpop, bdpop, dout);
}